// round 2
// baseline (speedup 1.0000x reference)
#include <cuda_runtime.h>

// RollingBufferCache: B=4, H=8, S=512, D=128, BUF=4096.
// Output = [k_window ; v_window], each [B,H,W,D] with W = min(cur, BUF).
// Since W == BUF here, every physical slot appears exactly once in the window,
// so scatter+gather collapses to a per-row source selection:
//   w >= W-S        -> new chunk row (w - (W-S))
//   otherwise       -> cache row (cur - W + w) & (BUF-1)

#define ROLL_D4   32    // D/4 float4 per row (D=128)
#define ROLL_BH   32    // B*H
#define ROLL_BUF  4096
#define ROLL_S    512

__global__ void __launch_bounds__(256)
RollingBufferCache_kernel(const float4* __restrict__ k,
                          const float4* __restrict__ v,
                          const float4* __restrict__ kc,
                          const float4* __restrict__ vc,
                          const int*    __restrict__ cur_p,
                          float4*       __restrict__ out,
                          int W)
{
    const int cur  = __ldg(cur_p);        // device scalar (graph-capturable)
    const int sel  = blockIdx.z;          // 0 = k path, 1 = v path
    const int bh   = blockIdx.y;          // flattened (b,h)
    const int lane = threadIdx.x & 31;
    const int warp = threadIdx.x >> 5;

    const float4* src_new = sel ? v  : k;
    const float4* src_old = sel ? vc : kc;
    float4* out_base = out + ((size_t)(sel * ROLL_BH + bh) * (size_t)W) * ROLL_D4;

    const int off    = cur - W;           // logical start of window
    const int wsplit = W - ROLL_S;        // rows >= wsplit come from new chunk

    // Each block covers 32 consecutive rows of one (sel,bh); 8 warps,
    // each warp does 4 rows (512 B each), one float4 per lane.
    #pragma unroll
    for (int r = 0; r < 4; ++r) {
        int w = blockIdx.x * 32 + r * 8 + warp;
        if (w >= W) break;

        const float4* srow;
        if (w >= wsplit) {
            srow = src_new + ((size_t)bh * ROLL_S + (size_t)(w - wsplit)) * ROLL_D4;
        } else {
            int phys = (off + w) & (ROLL_BUF - 1);
            srow = src_old + ((size_t)bh * ROLL_BUF + (size_t)phys) * ROLL_D4;
        }
        out_base[(size_t)w * ROLL_D4 + lane] = srow[lane];
    }
}

extern "C" void kernel_launch(void* const* d_in, const int* in_sizes, int n_in,
                              void* d_out, int out_size)
{
    const float4* k  = (const float4*)d_in[0];
    const float4* v  = (const float4*)d_in[1];
    const float4* kc = (const float4*)d_in[2];
    const float4* vc = (const float4*)d_in[3];
    const int*   cur = (const int*)d_in[4];

    // out_size = 2 * BH * W * D  ->  W
    const int W = out_size / (2 * ROLL_BH * 128);

    dim3 grid((W + 31) / 32, ROLL_BH, 2);
    RollingBufferCache_kernel<<<grid, 256>>>(k, v, kc, vc, cur,
                                             (float4*)d_out, W);
}

// round 3
// speedup vs baseline: 1.0042x; 1.0042x over previous
#include <cuda_runtime.h>

// RollingBufferCache: B=4, H=8, S=512, D=128, BUF=4096.
// Output = [k_window ; v_window], each [B,H,W,D] with W = min(cur, BUF).
// W == BUF here, so every physical slot appears exactly once in the window:
// the scatter+gather collapses to a per-row source selection:
//   w >= W-S  -> new chunk row (w - (W-S))
//   otherwise -> cache row (cur - W + w) & (BUF-1)
//
// R2: W is always a multiple of 32 for this grid, so the bounds check is
// removed; loads are explicitly front-batched (MLP_p1=4) and separated from
// the stores; streaming (evict-first) hints since all data is touched once.

#define ROLL_D4   32    // D/4 float4 per row (D=128)
#define ROLL_BH   32    // B*H
#define ROLL_BUF  4096
#define ROLL_S    512

__global__ void __launch_bounds__(256)
RollingBufferCache_kernel(const float4* __restrict__ k,
                          const float4* __restrict__ v,
                          const float4* __restrict__ kc,
                          const float4* __restrict__ vc,
                          const int*    __restrict__ cur_p,
                          float4*       __restrict__ out,
                          int W)
{
    const int cur  = __ldg(cur_p);        // device scalar (graph-capturable)
    const int sel  = blockIdx.z;          // 0 = k path, 1 = v path
    const int bh   = blockIdx.y;          // flattened (b,h)
    const int lane = threadIdx.x & 31;
    const int warp = threadIdx.x >> 5;

    const float4* src_new = sel ? v  : k;
    const float4* src_old = sel ? vc : kc;
    float4* out_base = out + ((size_t)(sel * ROLL_BH + bh) * (size_t)W) * ROLL_D4;

    const int off    = cur - W;           // logical start of window
    const int wsplit = W - ROLL_S;        // rows >= wsplit come from new chunk

    // Each block covers 32 consecutive rows of one (sel,bh); 8 warps,
    // each warp does 4 rows (512 B each), one float4 per lane.
    const int w0 = blockIdx.x * 32 + warp;

    // Phase 1: compute all 4 source addresses, issue all 4 loads (MLP=4).
    const float4* srow[4];
    #pragma unroll
    for (int r = 0; r < 4; ++r) {
        const int w = w0 + r * 8;
        if (w >= wsplit) {
            srow[r] = src_new + ((size_t)bh * ROLL_S + (size_t)(w - wsplit)) * ROLL_D4;
        } else {
            const int phys = (off + w) & (ROLL_BUF - 1);
            srow[r] = src_old + ((size_t)bh * ROLL_BUF + (size_t)phys) * ROLL_D4;
        }
    }

    float4 val[4];
    #pragma unroll
    for (int r = 0; r < 4; ++r)
        val[r] = __ldcs(srow[r] + lane);   // evict-first: single-use stream

    // Phase 2: store all 4 (streaming, evict-first).
    #pragma unroll
    for (int r = 0; r < 4; ++r)
        __stcs(out_base + (size_t)(w0 + r * 8) * ROLL_D4 + lane, val[r]);
}

extern "C" void kernel_launch(void* const* d_in, const int* in_sizes, int n_in,
                              void* d_out, int out_size)
{
    const float4* k  = (const float4*)d_in[0];
    const float4* v  = (const float4*)d_in[1];
    const float4* kc = (const float4*)d_in[2];
    const float4* vc = (const float4*)d_in[3];
    const int*   cur = (const int*)d_in[4];

    // out_size = 2 * BH * W * D  ->  W
    const int W = out_size / (2 * ROLL_BH * 128);

    dim3 grid((W + 31) / 32, ROLL_BH, 2);
    RollingBufferCache_kernel<<<grid, 256>>>(k, v, kc, vc, cur,
                                             (float4*)d_out, W);
}

// round 4
// speedup vs baseline: 1.0215x; 1.0172x over previous
#include <cuda_runtime.h>

// RollingBufferCache: B=4, H=8, S=512, D=128, BUF=4096.
// Output = [k_window ; v_window], each [B,H,W,D] with W = min(cur, BUF).
// W == BUF here, so every physical slot appears exactly once in the window:
// scatter+gather collapses to a per-row source selection:
//   w >= W-S  -> new chunk row (w - (W-S))
//   otherwise -> cache row (cur - W + w) & (BUF-1)
//
// R3: 256-bit (v8.f32) loads/stores — Blackwell LDG.E.256/STG.E.256 — to halve
// request count and L1tex wavefront-queue pressure. MLP=4 front-batched loads,
// streaming (.cs) policy on both sides.

#define ROLL_BH   32    // B*H
#define ROLL_BUF  4096
#define ROLL_S    512
#define CHUNKS_PER_ROW 16   // D=128 floats = 512B = 16 x 32B chunks

struct __align__(32) F8 { float4 lo, hi; };

__device__ __forceinline__ F8 ldcs256(const F8* p) {
    F8 v;
    asm volatile("ld.global.cs.v8.f32 {%0,%1,%2,%3,%4,%5,%6,%7}, [%8];"
        : "=f"(v.lo.x), "=f"(v.lo.y), "=f"(v.lo.z), "=f"(v.lo.w),
          "=f"(v.hi.x), "=f"(v.hi.y), "=f"(v.hi.z), "=f"(v.hi.w)
        : "l"(p));
    return v;
}

__device__ __forceinline__ void stcs256(F8* p, const F8& v) {
    asm volatile("st.global.cs.v8.f32 [%0], {%1,%2,%3,%4,%5,%6,%7,%8};"
        :: "l"(p),
           "f"(v.lo.x), "f"(v.lo.y), "f"(v.lo.z), "f"(v.lo.w),
           "f"(v.hi.x), "f"(v.hi.y), "f"(v.hi.z), "f"(v.hi.w)
        : "memory");
}

__global__ void __launch_bounds__(256)
RollingBufferCache_kernel(const F8* __restrict__ k,
                          const F8* __restrict__ v,
                          const F8* __restrict__ kc,
                          const F8* __restrict__ vc,
                          const int* __restrict__ cur_p,
                          F8*        __restrict__ out,
                          int W)
{
    const int cur  = __ldg(cur_p);        // device scalar (graph-capturable)
    const int sel  = blockIdx.z;          // 0 = k path, 1 = v path
    const int bh   = blockIdx.y;          // flattened (b,h)
    const int lane = threadIdx.x & 31;
    const int warp = threadIdx.x >> 5;

    const F8* src_new = sel ? v  : k;
    const F8* src_old = sel ? vc : kc;
    F8* out_base = out + ((size_t)(sel * ROLL_BH + bh) * (size_t)W) * CHUNKS_PER_ROW;

    const int off    = cur - W;           // logical start of window
    const int wsplit = W - ROLL_S;        // rows >= wsplit come from new chunk

    // Block = 8 warps x 8 rows = 64 rows. Each warp iteration covers 2 rows
    // (16 lanes x 32B per row); 4 iterations per warp, loads front-batched.
    const int wbase = blockIdx.x * 64 + warp * 8 + (lane >> 4);
    const int sub   = lane & 15;

    const F8* srow[4];
    int       wrow[4];
    #pragma unroll
    for (int r = 0; r < 4; ++r) {
        int w = wbase + 2 * r;
        wrow[r] = w;
        int wc = w < W ? w : W - 1;       // clamp keeps OOB loads safe, no divergence
        if (wc >= wsplit) {
            srow[r] = src_new + ((size_t)bh * ROLL_S + (size_t)(wc - wsplit)) * CHUNKS_PER_ROW;
        } else {
            int phys = (off + wc) & (ROLL_BUF - 1);
            srow[r] = src_old + ((size_t)bh * ROLL_BUF + (size_t)phys) * CHUNKS_PER_ROW;
        }
    }

    F8 val[4];
    #pragma unroll
    for (int r = 0; r < 4; ++r)
        val[r] = ldcs256(srow[r] + sub);

    #pragma unroll
    for (int r = 0; r < 4; ++r)
        if (wrow[r] < W)
            stcs256(out_base + (size_t)wrow[r] * CHUNKS_PER_ROW + sub, val[r]);
}

extern "C" void kernel_launch(void* const* d_in, const int* in_sizes, int n_in,
                              void* d_out, int out_size)
{
    const F8* k  = (const F8*)d_in[0];
    const F8* v  = (const F8*)d_in[1];
    const F8* kc = (const F8*)d_in[2];
    const F8* vc = (const F8*)d_in[3];
    const int* cur = (const int*)d_in[4];

    // out_size = 2 * BH * W * D  ->  W
    const int W = out_size / (2 * ROLL_BH * 128);

    dim3 grid((W + 63) / 64, ROLL_BH, 2);
    RollingBufferCache_kernel<<<grid, 256>>>(k, v, kc, vc, cur,
                                             (F8*)d_out, W);
}